// round 7
// baseline (speedup 1.0000x reference)
#include <cuda_runtime.h>
#include <cstdint>

#define TILE_N 32
#define THREADS 512
#define XS 1028            // x_s row stride (words) ≡ 4 (mod 32): conflict-free frag reads
#define OST_MAX 452        // out-stage row stride for lo=3 (64*7+4)

__device__ __forceinline__ unsigned f2tf_rna(float f) {
    unsigned u; asm("cvt.rna.tf32.f32 %0, %1;" : "=r"(u) : "f"(f)); return u;
}

#define MMA8(C, A0, A1, A2, A3, B0, B1)                                        \
    asm volatile("mma.sync.aligned.m16n8k8.row.col.f32.tf32.tf32.f32 "         \
        "{%0,%1,%2,%3}, {%4,%5,%6,%7}, {%8,%9}, {%0,%1,%2,%3};"                \
        : "+f"((C)[0]), "+f"((C)[1]), "+f"((C)[2]), "+f"((C)[3])               \
        : "r"(A0), "r"(A1), "r"(A2), "r"(A3), "r"(B0), "r"(B1))

__global__ __launch_bounds__(THREADS, 1)
void tp_kernel(const float* __restrict__ x, const float* __restrict__ W,
               const float* __restrict__ hzero, const float* __restrict__ hpos,
               const float* __restrict__ hneg, float* __restrict__ out)
{
    extern __shared__ float smem[];
    float* x_s = smem;                         // TILE_N * XS
    float* o_s = smem + TILE_N * XS;           // TILE_N * OST_MAX

    const int tid = threadIdx.x;
    const long long n0 = (long long)blockIdx.x * TILE_N;

    // ---- load x tile: 32 rows x 1024 floats, coalesced float4 ----
    {
        const float4* xg = (const float4*)(x + n0 * 1024);
        #pragma unroll
        for (int q = tid; q < TILE_N * 256; q += THREADS) {
            int r = q >> 8, c = q & 255;
            float4 v = xg[r * 256 + c];
            float* d = x_s + r * XS + (c << 2);
            d[0] = v.x; d[1] = v.y; d[2] = v.z; d[3] = v.w;
        }
    }
    __syncthreads();

    const int warp = tid >> 5, lane = tid & 31;
    const int wk = warp & 1;                       // K-half: 0 -> k[0,32), 1 -> k[32,64)
    const int wrest = warp >> 1;
    const int wm = wrest >> 2, wn = wrest & 3;     // 2 (M) x 4 (N)
    const int g  = lane >> 2, t4 = lane & 3;
    const int r0 = wm * 16 + g;
    const float* xrow0 = x_s + r0 * XS;
    const float* xrow1 = xrow0 + 8 * XS;

    #pragma unroll
    for (int oi = 0; oi < 4; ++oi) {
        const int lo = oi, so = 2 * oi + 1;
        const int offo = 64 * oi * oi;
        const int ost = 64 * so + 4;

        float acc[2][7][4];
        #pragma unroll
        for (int nt = 0; nt < 2; ++nt)
            #pragma unroll
            for (int co = 0; co <= 2 * oi; ++co) {
                acc[nt][co][0] = 0.f; acc[nt][co][1] = 0.f;
                acc[nt][co][2] = 0.f; acc[nt][co][3] = 0.f;
            }

        #pragma unroll
        for (int ii = 0; ii < 4; ++ii) {
            const int li = ii, si = 2 * ii + 1;
            const int base = 64 * ii * ii;
            const int p = (oi << 2) + ii;

            // ---- B (W) fragments straight from global (rna-rounded, loop-invariant) ----
            unsigned bw[2][4][2];
            {
                const float* Wp = W + p * 4096 + (wn * 16 + g) * 64 + 32 * wk + t4;
                #pragma unroll
                for (int nt = 0; nt < 2; ++nt)
                    #pragma unroll
                    for (int s = 0; s < 4; ++s) {
                        bw[nt][s][0] = f2tf_rna(__ldg(Wp + nt * 512 + 8 * s));
                        bw[nt][s][1] = f2tf_rna(__ldg(Wp + nt * 512 + 8 * s + 4));
                    }
            }

            const int kb = 32 * wk * si;               // K-half channel offset
            const float* xa0 = xrow0 + base + li + kb;
            const float* xa1 = xrow1 + base + li + kb;
            const float h0 = __ldg(hzero + p);

            // ---- m = 0 vgemm (A = fp32 bits, HW truncates to tf32) ----
            #pragma unroll
            for (int s = 0; s < 4; ++s) {
                int c0 = (t4 + 8 * s) * si, c1 = c0 + 4 * si;
                unsigned a0 = __float_as_uint(h0 * xa0[c0]);
                unsigned a1 = __float_as_uint(h0 * xa1[c0]);
                unsigned a2 = __float_as_uint(h0 * xa0[c1]);
                unsigned a3 = __float_as_uint(h0 * xa1[c1]);
                MMA8(acc[0][lo], a0, a1, a2, a3, bw[0][s][0], bw[0][s][1]);
                MMA8(acc[1][lo], a0, a1, a2, a3, bw[1][s][0], bw[1][s][1]);
            }

            // ---- m >= 1: fused (+m, -m) pair sharing x loads ----
            #pragma unroll
            for (int m = 1; m <= oi; ++m) {
                if (ii >= m) {
                    const float hp = __ldg(hpos + p * 3 + m - 1);
                    const float hn = __ldg(hneg + p * 3 + m - 1);
                    #pragma unroll
                    for (int s = 0; s < 4; ++s) {
                        int c0 = (t4 + 8 * s) * si, c1 = c0 + 4 * si;
                        float xp00 = xa0[c0 + m], xn00 = xa0[c0 - m];
                        float xp10 = xa1[c0 + m], xn10 = xa1[c0 - m];
                        float xp01 = xa0[c1 + m], xn01 = xa0[c1 - m];
                        float xp11 = xa1[c1 + m], xn11 = xa1[c1 - m];
                        unsigned u0 = __float_as_uint(hp * xp00 + hn * xn00);
                        unsigned u1 = __float_as_uint(hp * xp10 + hn * xn10);
                        unsigned u2 = __float_as_uint(hp * xp01 + hn * xn01);
                        unsigned u3 = __float_as_uint(hp * xp11 + hn * xn11);
                        unsigned v0 = __float_as_uint(hp * xn00 - hn * xp00);
                        unsigned v1 = __float_as_uint(hp * xn10 - hn * xp10);
                        unsigned v2 = __float_as_uint(hp * xn01 - hn * xp01);
                        unsigned v3 = __float_as_uint(hp * xn11 - hn * xp11);
                        MMA8(acc[0][lo + m], u0, u1, u2, u3, bw[0][s][0], bw[0][s][1]);
                        MMA8(acc[1][lo + m], u0, u1, u2, u3, bw[1][s][0], bw[1][s][1]);
                        MMA8(acc[0][lo - m], v0, v1, v2, v3, bw[0][s][0], bw[0][s][1]);
                        MMA8(acc[1][lo - m], v0, v1, v2, v3, bw[1][s][0], bw[1][s][1]);
                    }
                }
            }
        }

        // ---- epilogue: K-half reduce through o_s, then coalesced float4 stores ----
        __syncthreads();   // prior oi's store loop done reading o_s
        if (wk == 0) {
            #pragma unroll
            for (int nt = 0; nt < 2; ++nt) {
                int o0 = wn * 16 + nt * 8 + 2 * t4;
                #pragma unroll
                for (int co = 0; co <= 2 * oi; ++co) {
                    float* d0 = o_s + r0 * ost + o0 * so + co;
                    float* d1 = d0 + 8 * ost;
                    d0[0]  = acc[nt][co][0];
                    d0[so] = acc[nt][co][1];
                    d1[0]  = acc[nt][co][2];
                    d1[so] = acc[nt][co][3];
                }
            }
        }
        __syncthreads();
        if (wk == 1) {
            #pragma unroll
            for (int nt = 0; nt < 2; ++nt) {
                int o0 = wn * 16 + nt * 8 + 2 * t4;
                #pragma unroll
                for (int co = 0; co <= 2 * oi; ++co) {
                    float* d0 = o_s + r0 * ost + o0 * so + co;
                    float* d1 = d0 + 8 * ost;
                    d0[0]  += acc[nt][co][0];
                    d0[so] += acc[nt][co][1];
                    d1[0]  += acc[nt][co][2];
                    d1[so] += acc[nt][co][3];
                }
            }
        }
        __syncthreads();
        {
            const int nf4 = 16 * so;
            for (int q = tid; q < TILE_N * nf4; q += THREADS) {
                int r = q / nf4, c = q - r * nf4;
                float4 v = *(const float4*)(o_s + r * ost + (c << 2));
                *(float4*)(out + (n0 + r) * 1024 + offo + (c << 2)) = v;
            }
        }
    }
}

extern "C" void kernel_launch(void* const* d_in, const int* in_sizes, int n_in,
                              void* d_out, int out_size) {
    const float* x  = (const float*)d_in[0];
    const float* w  = (const float*)d_in[1];
    const float* hz = (const float*)d_in[2];
    const float* hp = (const float*)d_in[3];
    const float* hn = (const float*)d_in[4];
    float* out = (float*)d_out;

    const int n = in_sizes[0] / 1024;              // 65536
    const int grid = n / TILE_N;                   // 2048
    const int smem_bytes = (TILE_N * XS + TILE_N * OST_MAX) * 4; // 189440 B

    cudaFuncSetAttribute(tp_kernel, cudaFuncAttributeMaxDynamicSharedMemorySize, smem_bytes);
    tp_kernel<<<grid, THREADS, smem_bytes>>>(x, w, hz, hp, hn, out);
}

// round 8
// speedup vs baseline: 2.3724x; 2.3724x over previous
#include <cuda_runtime.h>
#include <cstdint>

#define TILE_N 32
#define THREADS 256
#define XS 1028            // x_s row stride (words) ≡ 4 (mod 32): conflict-free frag reads
#define WS 68              // w_s row stride ≡ 4 (mod 32)
#define WBUF (64 * WS)
#define OST_MAX 452        // out-stage row stride for lo=3 (64*7+4)

__device__ __forceinline__ unsigned f2tf_rna(float f) {
    unsigned u; asm("cvt.rna.tf32.f32 %0, %1;" : "=r"(u) : "f"(f)); return u;
}

__device__ __forceinline__ void cp16(float* dst, const float* src) {
    unsigned d = (unsigned)__cvta_generic_to_shared(dst);
    asm volatile("cp.async.cg.shared.global [%0], [%1], 16;" :: "r"(d), "l"(src));
}
__device__ __forceinline__ void cp_commit() {
    asm volatile("cp.async.commit_group;" ::: "memory");
}
__device__ __forceinline__ void cp_wait0() {
    asm volatile("cp.async.wait_group 0;" ::: "memory");
}

#define MMA8(C, A0, A1, A2, A3, B0, B1)                                        \
    asm volatile("mma.sync.aligned.m16n8k8.row.col.f32.tf32.tf32.f32 "         \
        "{%0,%1,%2,%3}, {%4,%5,%6,%7}, {%8,%9}, {%0,%1,%2,%3};"                \
        : "+f"((C)[0]), "+f"((C)[1]), "+f"((C)[2]), "+f"((C)[3])               \
        : "r"(A0), "r"(A1), "r"(A2), "r"(A3), "r"(B0), "r"(B1))

__global__ __launch_bounds__(THREADS, 1)
void tp_kernel(const float* __restrict__ x, const float* __restrict__ W,
               const float* __restrict__ hzero, const float* __restrict__ hpos,
               const float* __restrict__ hneg, float* __restrict__ out)
{
    extern __shared__ float smem[];
    float* x_s = smem;                          // TILE_N * XS
    float* w_s = smem + TILE_N * XS;            // 2 * WBUF (raw fp32, double-buffered)
    float* o_s = w_s + 2 * WBUF;                // TILE_N * OST_MAX

    const int tid = threadIdx.x;
    const long long n0 = (long long)blockIdx.x * TILE_N;

    // ---- issue W path-0 stage + full x tile via cp.async (one group) ----
    {
        #pragma unroll
        for (int q0 = 0; q0 < 4; ++q0) {
            int q = tid + q0 * THREADS;                       // 1024 float4
            cp16(w_s + (q >> 4) * WS + ((q & 15) << 2), W + q * 4);
        }
        const float* xg = x + n0 * 1024;
        #pragma unroll
        for (int q0 = 0; q0 < 32; ++q0) {
            int q = tid + q0 * THREADS;                       // 8192 float4
            cp16(x_s + (q >> 8) * XS + ((q & 255) << 2), xg + q * 4);
        }
        cp_commit();
    }

    const int warp = tid >> 5, lane = tid & 31;
    const int wm = warp >> 2, wn = warp & 3;       // 2 (M) x 4 (N) warp grid
    const int g  = lane >> 2, t4 = lane & 3;
    const int r0 = wm * 16 + g;
    const float* xrow0 = x_s + r0 * XS;
    const float* xrow1 = xrow0 + 8 * XS;

    #pragma unroll
    for (int oi = 0; oi < 4; ++oi) {
        const int lo = oi, so = 2 * oi + 1;
        const int offo = 64 * oi * oi;
        const int ost = 64 * so + 4;

        float acc[2][7][4];
        #pragma unroll
        for (int nt = 0; nt < 2; ++nt)
            #pragma unroll
            for (int co = 0; co <= 2 * oi; ++co) {
                acc[nt][co][0] = 0.f; acc[nt][co][1] = 0.f;
                acc[nt][co][2] = 0.f; acc[nt][co][3] = 0.f;
            }

        #pragma unroll
        for (int ii = 0; ii < 4; ++ii) {
            const int li = ii, si = 2 * ii + 1;
            const int base = 64 * ii * ii;
            const int p = (oi << 2) + ii;

            cp_wait0();          // stage p (issued one path ago) complete (this thread)
            __syncthreads();     // all threads' copies visible; prior path fully done

            if (p < 15) {        // prefetch next path's W into the other buffer
                const float* Wn = W + (p + 1) * 4096;
                float* wd = w_s + ((p + 1) & 1) * WBUF;
                #pragma unroll
                for (int q0 = 0; q0 < 4; ++q0) {
                    int q = tid + q0 * THREADS;
                    cp16(wd + (q >> 4) * WS + ((q & 15) << 2), Wn + q * 4);
                }
                cp_commit();
            }

            // ---- B (W) fragments from current buffer, cvt at frag load ----
            unsigned bw[2][8][2];
            {
                const float* wb = w_s + (p & 1) * WBUF + (wn * 16 + g) * WS + t4;
                #pragma unroll
                for (int nt = 0; nt < 2; ++nt)
                    #pragma unroll
                    for (int s = 0; s < 8; ++s) {
                        bw[nt][s][0] = f2tf_rna(wb[nt * 8 * WS + 8 * s]);
                        bw[nt][s][1] = f2tf_rna(wb[nt * 8 * WS + 8 * s + 4]);
                    }
            }

            const float* xa0 = xrow0 + base + li;
            const float* xa1 = xrow1 + base + li;
            const float h0 = __ldg(hzero + p);

            // ---- m = 0 vgemm (A = fp32 bits, HW truncates to tf32) ----
            #pragma unroll
            for (int s = 0; s < 8; ++s) {
                int c0 = (t4 + 8 * s) * si, c1 = c0 + 4 * si;
                unsigned a0 = __float_as_uint(h0 * xa0[c0]);
                unsigned a1 = __float_as_uint(h0 * xa1[c0]);
                unsigned a2 = __float_as_uint(h0 * xa0[c1]);
                unsigned a3 = __float_as_uint(h0 * xa1[c1]);
                MMA8(acc[0][lo], a0, a1, a2, a3, bw[0][s][0], bw[0][s][1]);
                MMA8(acc[1][lo], a0, a1, a2, a3, bw[1][s][0], bw[1][s][1]);
            }

            // ---- m >= 1: fused (+m, -m) pair sharing x loads ----
            #pragma unroll
            for (int m = 1; m <= oi; ++m) {
                if (ii >= m) {
                    const float hp = __ldg(hpos + p * 3 + m - 1);
                    const float hn = __ldg(hneg + p * 3 + m - 1);
                    #pragma unroll
                    for (int s = 0; s < 8; ++s) {
                        int c0 = (t4 + 8 * s) * si, c1 = c0 + 4 * si;
                        float xp00 = xa0[c0 + m], xn00 = xa0[c0 - m];
                        float xp10 = xa1[c0 + m], xn10 = xa1[c0 - m];
                        float xp01 = xa0[c1 + m], xn01 = xa0[c1 - m];
                        float xp11 = xa1[c1 + m], xn11 = xa1[c1 - m];
                        unsigned u0 = __float_as_uint(hp * xp00 + hn * xn00);
                        unsigned u1 = __float_as_uint(hp * xp10 + hn * xn10);
                        unsigned u2 = __float_as_uint(hp * xp01 + hn * xn01);
                        unsigned u3 = __float_as_uint(hp * xp11 + hn * xn11);
                        unsigned v0 = __float_as_uint(hp * xn00 - hn * xp00);
                        unsigned v1 = __float_as_uint(hp * xn10 - hn * xp10);
                        unsigned v2 = __float_as_uint(hp * xn01 - hn * xp01);
                        unsigned v3 = __float_as_uint(hp * xn11 - hn * xp11);
                        MMA8(acc[0][lo + m], u0, u1, u2, u3, bw[0][s][0], bw[0][s][1]);
                        MMA8(acc[1][lo + m], u0, u1, u2, u3, bw[1][s][0], bw[1][s][1]);
                        MMA8(acc[0][lo - m], v0, v1, v2, v3, bw[0][s][0], bw[0][s][1]);
                        MMA8(acc[1][lo - m], v0, v1, v2, v3, bw[1][s][0], bw[1][s][1]);
                    }
                }
            }
        }

        // ---- epilogue: regs -> interleaved stage -> coalesced float4 global ----
        // (prior oi's o_s reads are fenced by this oi's ii=0 barrier)
        #pragma unroll
        for (int nt = 0; nt < 2; ++nt) {
            int o0 = wn * 16 + nt * 8 + 2 * t4;
            #pragma unroll
            for (int co = 0; co <= 2 * oi; ++co) {
                float* d0 = o_s + r0 * ost + o0 * so + co;
                float* d1 = d0 + 8 * ost;
                d0[0]  = acc[nt][co][0];
                d0[so] = acc[nt][co][1];
                d1[0]  = acc[nt][co][2];
                d1[so] = acc[nt][co][3];
            }
        }
        __syncthreads();
        {
            const int nf4 = 16 * so;
            for (int q = tid; q < TILE_N * nf4; q += THREADS) {
                int r = q / nf4, c = q - r * nf4;
                float4 v = *(const float4*)(o_s + r * ost + (c << 2));
                *(float4*)(out + (n0 + r) * 1024 + offo + (c << 2)) = v;
            }
        }
    }
}

extern "C" void kernel_launch(void* const* d_in, const int* in_sizes, int n_in,
                              void* d_out, int out_size) {
    const float* x  = (const float*)d_in[0];
    const float* w  = (const float*)d_in[1];
    const float* hz = (const float*)d_in[2];
    const float* hp = (const float*)d_in[3];
    const float* hn = (const float*)d_in[4];
    float* out = (float*)d_out;

    const int n = in_sizes[0] / 1024;              // 65536
    const int grid = n / TILE_N;                   // 2048
    const int smem_bytes = (TILE_N * XS + 2 * WBUF + TILE_N * OST_MAX) * 4; // 224256 B

    cudaFuncSetAttribute(tp_kernel, cudaFuncAttributeMaxDynamicSharedMemorySize, smem_bytes);
    tp_kernel<<<grid, THREADS, smem_bytes>>>(x, w, hz, hp, hn, out);
}